// round 9
// baseline (speedup 1.0000x reference)
#include <cuda_runtime.h>
#include <cuda_bf16.h>
#include <cstdint>

// SSIM loss map: out = clip((1 - SSIM_3x3(x,y)) * 0.5, 0, 1)
// NCHW fp32, 16x3x512x512 = 48 planes of 512x512.
// Register-sliding, no shared memory, packed f32x2 math, one-iteration
// software pipeline. Addressing is pointer + compile-time-constant offsets;
// bounds checks and the edge-row normalization exist only in the (few)
// unrolled iterations where they can actually trigger.

#define IMG   512
#define ROWS  16          // output rows per thread
#define TPX   128         // threads per block; block covers TPX*2 = 256 cols

typedef unsigned long long u64;

// ---- packed f32x2 helpers (sm_100+) ----
__device__ __forceinline__ u64 pk(float x, float y) {
    u64 r; asm("mov.b64 %0, {%1, %2};" : "=l"(r) : "f"(x), "f"(y)); return r;
}
__device__ __forceinline__ float2 unpk(u64 v) {
    float2 r; asm("mov.b64 {%0, %1}, %2;" : "=f"(r.x), "=f"(r.y) : "l"(v)); return r;
}
__device__ __forceinline__ u64 add2(u64 a, u64 b) {
    u64 r; asm("add.rn.f32x2 %0, %1, %2;" : "=l"(r) : "l"(a), "l"(b)); return r;
}
__device__ __forceinline__ u64 sub2(u64 a, u64 b) {
    u64 r; asm("sub.rn.f32x2 %0, %1, %2;" : "=l"(r) : "l"(a), "l"(b)); return r;
}
__device__ __forceinline__ u64 mul2(u64 a, u64 b) {
    u64 r; asm("mul.rn.f32x2 %0, %1, %2;" : "=l"(r) : "l"(a), "l"(b)); return r;
}
__device__ __forceinline__ u64 fma2(u64 a, u64 b, u64 c) {
    u64 r; asm("fma.rn.f32x2 %0, %1, %2, %3;" : "=l"(r) : "l"(a), "l"(b), "l"(c)); return r;
}

// Raw row data: this thread's float2 from x and y, plus prefetched edge
// neighbor scalars (only meaningful in lanes 0 / 31).
struct Raw { float2 a, b; float eLa, eLb, eRa, eRb; };

// Horizontal 3-tap sums for the thread's 2 output columns, packed f32x2.
struct Stat { u64 x, y, xx, yy, xy; };

// Prefetch: LDGs only. doff is a compile-time constant at every call site
// after unrolling; valid is a literal `true` for all interior iterations.
__device__ __forceinline__ Raw load_raw(const float* __restrict__ px,
                                        const float* __restrict__ py,
                                        int doff, bool valid,
                                        bool doL, bool doR)
{
    Raw r;
    r.a = make_float2(0.f, 0.f); r.b = make_float2(0.f, 0.f);
    r.eLa = r.eLb = r.eRa = r.eRb = 0.f;
    if (valid) {
        r.a = *(const float2*)(px + doff);
        r.b = *(const float2*)(py + doff);
        if (doL) { r.eLa = px[doff - 1]; r.eLb = py[doff - 1]; }
        if (doR) { r.eRa = px[doff + 2]; r.eRb = py[doff + 2]; }
    }
    return r;
}

// Consume: shuffles (on registers loaded >= 1 iteration ago) + h-stats.
__device__ __forceinline__ Stat make_stats(const Raw& w, bool pl, bool pr)
{
    float aL = __shfl_up_sync(0xffffffffu, w.a.y, 1);
    float bL = __shfl_up_sync(0xffffffffu, w.b.y, 1);
    float aR = __shfl_down_sync(0xffffffffu, w.a.x, 1);
    float bR = __shfl_down_sync(0xffffffffu, w.b.x, 1);
    if (pl) { aL = w.eLa; bL = w.eLb; }
    if (pr) { aR = w.eRa; bR = w.eRb; }

    Stat s;
    float sa = w.a.x + w.a.y;
    s.x = pk(aL + sa, sa + aR);
    float sb = w.b.x + w.b.y;
    s.y = pk(bL + sb, sb + bR);
    float pa = fmaf(w.a.x, w.a.x, w.a.y * w.a.y);
    s.xx = pk(fmaf(aL, aL, pa), fmaf(aR, aR, pa));
    float pb = fmaf(w.b.x, w.b.x, w.b.y * w.b.y);
    s.yy = pk(fmaf(bL, bL, pb), fmaf(bR, bR, pb));
    float pm = fmaf(w.a.x, w.b.x, w.a.y * w.b.y);
    s.xy = pk(fmaf(aL, bL, pm), fmaf(aR, bR, pm));
    return s;
}

__global__ __launch_bounds__(TPX)
void ssim_kernel(const float* __restrict__ gx,
                 const float* __restrict__ gy,
                 float* __restrict__ gout)
{
    const int tx   = threadIdx.x;
    const int lane = tx & 31;
    const bool pl = (lane == 0);
    const bool pr = (lane == 31);
    const int c2 = blockIdx.x * TPX + tx;       // float2 index, 0..255
    const bool doL = pl && (c2 > 0);
    const bool doR = pr && (c2 < IMG / 2 - 1);
    const int h0 = blockIdx.y * ROWS;

    // per-thread base pointers at (row h0, col 2*c2); all further addressing
    // is compile-time-constant offsets from these
    const size_t base = (size_t)blockIdx.z * (IMG * IMG);
    const int toff = h0 * IMG + 2 * c2;
    const float* px = gx + base + toff;
    const float* py = gy + base + toff;
    float2* pout = (float2*)(gout + base) + (h0 * (IMG / 2) + c2);

    const float THIRD = 1.f / 3.f;
    float2 rcx = make_float2(c2 == 0 ? 0.5f : THIRD,
                             c2 == (IMG / 2 - 1) ? 0.5f : THIRD);

    const u64 TWO2 = pk(2.f, 2.f);
    const u64 C12  = pk(1e-4f, 1e-4f);
    const u64 C22  = pk(9e-4f, 9e-4f);
    const u64 EPS2 = pk(1e-12f, 1e-12f);
    const u64 inv3 = pk(rcx.x * THIRD, rcx.y * THIRD);   // interior rows (cy==3)

    // Pipeline fill. Rolling state: pc = stats(h-1)+stats(h), c = stats(h).
    Stat p0 = make_stats(load_raw(px, py, -IMG, h0 > 0, doL, doR), pl, pr);
    Stat c  = make_stats(load_raw(px, py, 0, true, doL, doR), pl, pr);
    Stat pc;
    pc.x  = add2(p0.x,  c.x);
    pc.y  = add2(p0.y,  c.y);
    pc.xx = add2(p0.xx, c.xx);
    pc.yy = add2(p0.yy, c.yy);
    pc.xy = add2(p0.xy, c.xy);
    Raw rn = load_raw(px, py, IMG, true, doL, doR);

    #pragma unroll
    for (int r = 0; r < ROWS; r++) {
        // prefetch row h0+r+2: in-bounds by construction unless this is the
        // last y-block AND r >= ROWS-2 (both compile-time except h0 compare)
        const bool valid = (r < ROWS - 2) || (h0 < IMG - ROWS);
        Raw rf = load_raw(px, py, (r + 2) * IMG, valid, doL, doR);

        // consume the row prefetched last iteration
        Stat n = make_stats(rn, pl, pr);

        // normalization: cy != 3 only possible at iterations 0 and ROWS-1
        u64 inv = inv3;
        if ((r == 0 && h0 == 0) || (r == ROWS - 1 && h0 == IMG - ROWS))
            inv = pk(rcx.x * 0.5f, rcx.y * 0.5f);

        // vertical 3-tap totals and window shift
        u64 Sx  = add2(pc.x,  n.x);
        u64 Sy  = add2(pc.y,  n.y);
        u64 Sxx = add2(pc.xx, n.xx);
        u64 Syy = add2(pc.yy, n.yy);
        u64 Sxy = add2(pc.xy, n.xy);

        pc.x  = add2(c.x,  n.x);
        pc.y  = add2(c.y,  n.y);
        pc.xx = add2(c.xx, n.xx);
        pc.yy = add2(c.yy, n.yy);
        pc.xy = add2(c.xy, n.xy);
        c = n;

        // packed SSIM epilogue
        u64 mux = mul2(Sx, inv);
        u64 muy = mul2(Sy, inv);
        u64 mmx  = mul2(mux, mux);
        u64 mmy  = mul2(muy, muy);
        u64 mmxy = mul2(mux, muy);
        u64 sigx  = sub2(mul2(Sxx, inv), mmx);
        u64 sigy  = sub2(mul2(Syy, inv), mmy);
        u64 sigxy = sub2(mul2(Sxy, inv), mmxy);

        u64 t1  = fma2(mmxy, TWO2, C12);
        u64 t2  = fma2(sigxy, TWO2, C22);
        u64 num = mul2(t1, t2);
        u64 d1  = add2(add2(mmx, mmy), C12);
        u64 d2  = add2(add2(sigx, sigy), C22);
        u64 den = fma2(d1, d2, EPS2);

        float2 fn = unpk(num);
        float2 fd = unpk(den);
        float s0 = __fdividef(fn.x, fd.x);
        float s1 = __fdividef(fn.y, fd.y);
        float2 o;
        o.x = fminf(fmaxf(fmaf(s0, -0.5f, 0.5f), 0.f), 1.f);
        o.y = fminf(fmaxf(fmaf(s1, -0.5f, 0.5f), 0.f), 1.f);

        pout[r * (IMG / 2)] = o;

        rn = rf;
    }
}

extern "C" void kernel_launch(void* const* d_in, const int* in_sizes, int n_in,
                              void* d_out, int out_size)
{
    const float* x = (const float*)d_in[0];
    const float* y = (const float*)d_in[1];
    float* out = (float*)d_out;

    dim3 block(TPX, 1, 1);                            // 128 threads
    dim3 grid(IMG / (2 * TPX), IMG / ROWS, 16 * 3);   // 2 x 32 x 48 = 3072
    ssim_kernel<<<grid, block>>>(x, y, out);
}